// round 7
// baseline (speedup 1.0000x reference)
#include <cuda_runtime.h>
#include <cuda_fp16.h>
#include <cstdint>

// Problem constants
#define BB    8
#define CINN  64
#define COUTN 64
#define HH    512
#define WWW   512

#define NCH        4                       // cin chunks of 16
// weights smem: [ch(4)][tap(9)][khalf(2)][cout(64) x 16B]
#define W_BYTES    (NCH * 9 * 2 * 64 * 16) // 73728
// x stage smem: [row(3)][khalf(2)][px(520) x 16B]  (514 used: gx -1..512)
#define XPLANE     (520 * 16)              // 8320
#define XROW_BYTES (2 * XPLANE)            // 16640
#define XSTAGE     (3 * XROW_BYTES)        // 49920
#define NSTAGE     3
#define SMEM_DYN   (W_BYTES + NSTAGE * XSTAGE)  // 223488

// x transposed+converted: [b][y][w][64 cins fp16] (plain layout)
__device__ __half g_xh[(size_t)BB * HH * WWW * CINN];
// demodulated fp16 weights: [b][ch][tap][khalf][cout][8 k-halves]
__device__ __half g_wsh[(size_t)BB * NCH * 9 * 2 * 64 * 8];

// ---------------------------------------------------------------------------
// helpers
// ---------------------------------------------------------------------------
__device__ __forceinline__ uint32_t smem_u32(const void* p) {
    uint32_t a;
    asm("{ .reg .u64 t; cvta.to.shared.u64 t, %1; cvt.u32.u64 %0, t; }" : "=r"(a) : "l"(p));
    return a;
}
__device__ __forceinline__ void cp16(uint32_t d, const void* s) {
    asm volatile("cp.async.cg.shared.global [%0], [%1], 16;" :: "r"(d), "l"(s) : "memory");
}
__device__ __forceinline__ void cp16z(uint32_t d, const void* s, uint32_t sz) {
    asm volatile("cp.async.cg.shared.global [%0], [%1], 16, %2;"
                 :: "r"(d), "l"(s), "r"(sz) : "memory");
}
__device__ __forceinline__ void cp_commit() {
    asm volatile("cp.async.commit_group;" ::: "memory");
}
template <int N>
__device__ __forceinline__ void cp_wait() {
    asm volatile("cp.async.wait_group %0;" :: "n"(N) : "memory");
}
__device__ __forceinline__ void ldsm4(uint32_t& r0, uint32_t& r1, uint32_t& r2,
                                      uint32_t& r3, uint32_t addr) {
    asm volatile("ldmatrix.sync.aligned.m8n8.x4.shared.b16 {%0,%1,%2,%3}, [%4];"
                 : "=r"(r0), "=r"(r1), "=r"(r2), "=r"(r3) : "r"(addr));
}
__device__ __forceinline__ void mma_f16(float* d,
                                        uint32_t a0, uint32_t a1, uint32_t a2, uint32_t a3,
                                        uint32_t b0, uint32_t b1) {
    asm("mma.sync.aligned.m16n8k16.row.col.f32.f16.f16.f32 "
        "{%0,%1,%2,%3},{%4,%5,%6,%7},{%8,%9},{%0,%1,%2,%3};"
        : "+f"(d[0]), "+f"(d[1]), "+f"(d[2]), "+f"(d[3])
        : "r"(a0), "r"(a1), "r"(a2), "r"(a3), "r"(b0), "r"(b1));
}

// ---------------------------------------------------------------------------
// Kernel 0: transpose + fp16-convert x -> g_xh[b][y][w][64] (plain)
// grid (16, 512, 8), 256 threads; tile = 32 px x 64 cins.
// ---------------------------------------------------------------------------
__global__ void __launch_bounds__(256)
transpose_kernel(const float* __restrict__ x) {
    __shared__ __half s[64][33];

    const int b  = blockIdx.z;
    const int y  = blockIdx.y;
    const int x0 = blockIdx.x * 32;
    const int tid  = threadIdx.x;
    const int wid  = tid >> 5;
    const int lane = tid & 31;

#pragma unroll
    for (int it = 0; it < 8; ++it) {
        const int cin = wid + it * 8;
        const float v = x[(((size_t)(b * CINN + cin) * HH) + y) * WWW + x0 + lane];
        s[cin][lane] = __float2half_rn(v);
    }
    __syncthreads();

    const int px    = tid >> 3;
    const int group = tid & 7;
    ushort h[8];
#pragma unroll
    for (int k = 0; k < 8; ++k)
        h[k] = __half_as_ushort(s[group * 8 + k][px]);
    uint4 v;
    v.x = (uint32_t)h[0] | ((uint32_t)h[1] << 16);
    v.y = (uint32_t)h[2] | ((uint32_t)h[3] << 16);
    v.z = (uint32_t)h[4] | ((uint32_t)h[5] << 16);
    v.w = (uint32_t)h[6] | ((uint32_t)h[7] << 16);
    __half* dst = g_xh + ((((size_t)b * HH + y) * WWW) + x0 + px) * CINN + group * 8;
    *reinterpret_cast<uint4*>(dst) = v;
}

// ---------------------------------------------------------------------------
// Kernel 1: modulate + demodulate -> fp16 weights [b][ch][tap][khalf][cout][8]
// ---------------------------------------------------------------------------
__global__ void modulate_kernel(const float* __restrict__ w,
                                const float* __restrict__ weight) {
    const int cout = blockIdx.x;
    const int b    = blockIdx.y;
    const int cin  = threadIdx.x;

    const float scale = 1.0f / 24.0f;  // 1/sqrt(64*9)
    const float wv = w[b * CINN + cin] * scale;

    float v[9];
    float ss = 0.0f;
#pragma unroll
    for (int kk = 0; kk < 9; ++kk) {
        float t = weight[(cout * CINN + cin) * 9 + kk] * wv;
        v[kk] = t;
        ss += t * t;
    }

    __shared__ float red[64];
    red[cin] = ss;
    __syncthreads();
    if (cin < 32) {
        float s = red[cin] + red[cin + 32];
#pragma unroll
        for (int off = 16; off > 0; off >>= 1)
            s += __shfl_down_sync(0xffffffffu, s, off);
        if (cin == 0) red[0] = s;
    }
    __syncthreads();

    const float d = rsqrtf(red[0] + 1e-8f);
    const int ch = cin >> 4;
    const int kh = (cin >> 3) & 1;
    const int ki = cin & 7;
#pragma unroll
    for (int kk = 0; kk < 9; ++kk) {
        g_wsh[((((((size_t)b * NCH + ch) * 9 + kk) * 2 + kh) * 64) + cout) * 8 + ki] =
            __float2half_rn(v[kk] * d);
    }
}

// ---------------------------------------------------------------------------
// Kernel 2: FP16 mma.sync implicit-GEMM conv, ldmatrix + 3-stage cp.async.
// grid (512 y, 8 b), 256 threads (8 warps), 1 CTA/SM (223.5KB smem).
// CTA tile: 64 couts x 512 px (full row). Warp: 64 couts x 64 px.
// Weights for all 4 chunks resident; steady-state fills are x-only.
// ---------------------------------------------------------------------------
__global__ void __launch_bounds__(256)
conv_mma_kernel(float* __restrict__ out) {
    extern __shared__ char smem[];
    const uint32_t sw = smem_u32(smem);
    const uint32_t sx = sw + W_BYTES;

    const int y = blockIdx.x;
    const int b = blockIdx.y;

    const int tid  = threadIdx.x;
    const int wid  = tid >> 5;     // pixel 64-group
    const int lane = tid & 31;
    const int t    = lane & 3;
    const int g    = lane >> 2;
    const int W0   = wid * 64;

    float acc[4][8][4];
#pragma unroll
    for (int mt = 0; mt < 4; ++mt)
#pragma unroll
        for (int nt = 0; nt < 8; ++nt)
#pragma unroll
            for (int i = 0; i < 4; ++i) acc[mt][nt][i] = 0.0f;

    // per-lane static ldmatrix address parts
    const uint32_t aw_lane = sw + (uint32_t)((lane >> 4) * 1024 + (lane & 15) * 16);
    const uint32_t xb_lane = (uint32_t)(((lane >> 3) & 1) * XPLANE +
                                        (W0 + (lane & 7) + ((lane >> 4) << 3)) * 16);

    // ---- weight fill: all 4 chunks, once ----
    {
        const char* wsrc = (const char*)g_wsh + (size_t)b * W_BYTES;
#pragma unroll
        for (int k = 0; k < 18; ++k) {
            const int idx = tid + k * 256;
            cp16(sw + idx * 16, wsrc + (size_t)idx * 16);
        }
    }

    // ---- x stage fill ----
    auto fill_x = [&](int ch, int stage) {
        const uint32_t ss = sx + stage * XSTAGE;
#pragma unroll
        for (int row = 0; row < 3; ++row) {
            const int yy  = y + row - 1;
            const bool yok = ((unsigned)yy < (unsigned)HH);
            const __half* src =
                g_xh + (((size_t)b * HH + (yok ? yy : 0)) * WWW) * CINN + ch * 16;
            const uint32_t dst0 = ss + row * XROW_BYTES;
#pragma unroll
            for (int i = tid; i < 514 * 2; i += 256) {
                const int px   = i >> 1;
                const int half = i & 1;
                const int gx   = px - 1;
                const bool ok  = yok && ((unsigned)gx < (unsigned)WWW);
                const int gxc  = gx < 0 ? 0 : (gx > WWW - 1 ? WWW - 1 : gx);
                cp16z(dst0 + half * XPLANE + px * 16,
                      src + (size_t)gxc * CINN + half * 8, ok ? 16u : 0u);
            }
        }
    };

    // ---- compute one 16-cin chunk ----
    auto compute = [&](int ch, int stage) {
        const uint32_t awc = aw_lane + (uint32_t)(ch * 9 * 2048);
        const uint32_t abs0 = sx + stage * XSTAGE + xb_lane;

#pragma unroll
        for (int tap = 0; tap < 9; ++tap) {
            const int dy = tap / 3;
            const int dx = tap - dy * 3;
            const uint32_t aw = awc + (uint32_t)tap * 2048;
            const uint32_t ab = abs0 + (uint32_t)dy * XROW_BYTES + (uint32_t)dx * 16;

            // A fragments: 4 m-tiles, 1 ldmatrix.x4 each
            uint32_t A[4][4];
#pragma unroll
            for (int mt = 0; mt < 4; ++mt)
                ldsm4(A[mt][0], A[mt][1], A[mt][2], A[mt][3],
                      aw + (uint32_t)(mt * 256));

            // B fragments: 4 ldmatrix.x4, each covers 2 n-tiles
#pragma unroll
            for (int np = 0; np < 4; ++np) {
                uint32_t b0, b1, b2, b3;
                ldsm4(b0, b1, b2, b3, ab + (uint32_t)(np * 256));
#pragma unroll
                for (int mt = 0; mt < 4; ++mt) {
                    mma_f16(acc[mt][2 * np + 0], A[mt][0], A[mt][1], A[mt][2],
                            A[mt][3], b0, b1);
                    mma_f16(acc[mt][2 * np + 1], A[mt][0], A[mt][1], A[mt][2],
                            A[mt][3], b2, b3);
                }
            }
        }
    };

    // ---- pipeline: weights+stage0 in G0; stages 1,2 in G1,G2 ----
    fill_x(0, 0);
    cp_commit();
    fill_x(1, 1);
    cp_commit();
    fill_x(2, 2);
    cp_commit();

#pragma unroll 1
    for (int ch = 0; ch < NCH; ++ch) {
        if (ch <= 1) cp_wait<2>();
        else if (ch == 2) cp_wait<1>();
        else cp_wait<0>();
        __syncthreads();
        compute(ch, ch % 3);
        __syncthreads();
        if (ch + 3 < NCH + 0) { /* never for NCH=4 beyond ch=0 */ }
        if (ch + 3 < NCH) { fill_x(ch + 3, (ch + 3) % 3); cp_commit(); }
        else if (ch == 0) { fill_x(3, 0); cp_commit(); }
    }

    // ---- epilogue: float2 stores ----
#pragma unroll
    for (int mt = 0; mt < 4; ++mt) {
        const int cout0 = mt * 16 + g;
#pragma unroll
        for (int nt = 0; nt < 8; ++nt) {
            const int px = W0 + nt * 8 + 2 * t;
            float* p0 = out + (((size_t)(b * COUTN + cout0)) * HH + y) * WWW + px;
            float* p1 = out + (((size_t)(b * COUTN + cout0 + 8)) * HH + y) * WWW + px;
            *(float2*)p0 = make_float2(acc[mt][nt][0], acc[mt][nt][1]);
            *(float2*)p1 = make_float2(acc[mt][nt][2], acc[mt][nt][3]);
        }
    }
}

// ---------------------------------------------------------------------------
extern "C" void kernel_launch(void* const* d_in, const int* in_sizes, int n_in,
                              void* d_out, int out_size) {
    const float* x      = (const float*)d_in[0];   // [8,64,512,512]
    const float* w      = (const float*)d_in[1];   // [8,64]
    const float* weight = (const float*)d_in[2];   // [64,64,3,3]
    float* out = (float*)d_out;                    // [8,64,512,512]

    cudaFuncSetAttribute(conv_mma_kernel,
                         cudaFuncAttributeMaxDynamicSharedMemorySize, SMEM_DYN);

    transpose_kernel<<<dim3(WWW / 32, HH, BB), 256>>>(x);
    modulate_kernel<<<dim3(COUTN, BB), 64>>>(w, weight);
    conv_mma_kernel<<<dim3(HH, BB), 256, SMEM_DYN>>>(out);
}

// round 8
// speedup vs baseline: 1.0276x; 1.0276x over previous
#include <cuda_runtime.h>
#include <cuda_fp16.h>
#include <cstdint>

// Problem constants
#define BB    8
#define CINN  64
#define COUTN 64
#define HH    512
#define WWW   512

#define NCH        4                       // cin chunks of 16
// weights smem: [ch(4)][tap(9)][khalf(2)][cout(64) x 16B]
#define W_BYTES    (NCH * 9 * 2 * 64 * 16) // 73728
// x stage smem: [row(3)][khalf(2)][px(520) x 16B]  (514 used: gx -1..512)
#define XPLANE     (520 * 16)              // 8320
#define XROW_BYTES (2 * XPLANE)            // 16640
#define XSTAGE     (3 * XROW_BYTES)        // 49920
#define NSTAGE     3
#define SMEM_DYN   (W_BYTES + NSTAGE * XSTAGE)  // 223488

// x transposed+converted: [b][y][w][64 cins fp16] (plain layout)
__device__ __half g_xh[(size_t)BB * HH * WWW * CINN];
// demodulated fp16 weights: [b][ch][tap][khalf][cout][8 k-halves]
__device__ __half g_wsh[(size_t)BB * NCH * 9 * 2 * 64 * 8];

// ---------------------------------------------------------------------------
// helpers
// ---------------------------------------------------------------------------
__device__ __forceinline__ uint32_t smem_u32(const void* p) {
    uint32_t a;
    asm("{ .reg .u64 t; cvta.to.shared.u64 t, %1; cvt.u32.u64 %0, t; }" : "=r"(a) : "l"(p));
    return a;
}
__device__ __forceinline__ void cp16(uint32_t d, const void* s) {
    asm volatile("cp.async.cg.shared.global [%0], [%1], 16;" :: "r"(d), "l"(s) : "memory");
}
__device__ __forceinline__ void cp16z(uint32_t d, const void* s, uint32_t sz) {
    asm volatile("cp.async.cg.shared.global [%0], [%1], 16, %2;"
                 :: "r"(d), "l"(s), "r"(sz) : "memory");
}
__device__ __forceinline__ void cp_commit() {
    asm volatile("cp.async.commit_group;" ::: "memory");
}
template <int N>
__device__ __forceinline__ void cp_wait() {
    asm volatile("cp.async.wait_group %0;" :: "n"(N) : "memory");
}
__device__ __forceinline__ void ldsm4(uint32_t& r0, uint32_t& r1, uint32_t& r2,
                                      uint32_t& r3, uint32_t addr) {
    asm volatile("ldmatrix.sync.aligned.m8n8.x4.shared.b16 {%0,%1,%2,%3}, [%4];"
                 : "=r"(r0), "=r"(r1), "=r"(r2), "=r"(r3) : "r"(addr));
}
__device__ __forceinline__ void mma_f16(float* d,
                                        uint32_t a0, uint32_t a1, uint32_t a2, uint32_t a3,
                                        uint32_t b0, uint32_t b1) {
    asm("mma.sync.aligned.m16n8k16.row.col.f32.f16.f16.f32 "
        "{%0,%1,%2,%3},{%4,%5,%6,%7},{%8,%9},{%0,%1,%2,%3};"
        : "+f"(d[0]), "+f"(d[1]), "+f"(d[2]), "+f"(d[3])
        : "r"(a0), "r"(a1), "r"(a2), "r"(a3), "r"(b0), "r"(b1));
}

// ---------------------------------------------------------------------------
// Kernel 0: transpose + fp16-convert x -> g_xh[b][y][w][64] (plain)
// ---------------------------------------------------------------------------
__global__ void __launch_bounds__(256)
transpose_kernel(const float* __restrict__ x) {
    __shared__ __half s[64][33];

    const int b  = blockIdx.z;
    const int y  = blockIdx.y;
    const int x0 = blockIdx.x * 32;
    const int tid  = threadIdx.x;
    const int wid  = tid >> 5;
    const int lane = tid & 31;

#pragma unroll
    for (int it = 0; it < 8; ++it) {
        const int cin = wid + it * 8;
        const float v = x[(((size_t)(b * CINN + cin) * HH) + y) * WWW + x0 + lane];
        s[cin][lane] = __float2half_rn(v);
    }
    __syncthreads();

    const int px    = tid >> 3;
    const int group = tid & 7;
    ushort h[8];
#pragma unroll
    for (int k = 0; k < 8; ++k)
        h[k] = __half_as_ushort(s[group * 8 + k][px]);
    uint4 v;
    v.x = (uint32_t)h[0] | ((uint32_t)h[1] << 16);
    v.y = (uint32_t)h[2] | ((uint32_t)h[3] << 16);
    v.z = (uint32_t)h[4] | ((uint32_t)h[5] << 16);
    v.w = (uint32_t)h[6] | ((uint32_t)h[7] << 16);
    __half* dst = g_xh + ((((size_t)b * HH + y) * WWW) + x0 + px) * CINN + group * 8;
    *reinterpret_cast<uint4*>(dst) = v;
}

// ---------------------------------------------------------------------------
// Kernel 1: modulate + demodulate -> fp16 weights [b][ch][tap][khalf][cout][8]
// ---------------------------------------------------------------------------
__global__ void modulate_kernel(const float* __restrict__ w,
                                const float* __restrict__ weight) {
    const int cout = blockIdx.x;
    const int b    = blockIdx.y;
    const int cin  = threadIdx.x;

    const float scale = 1.0f / 24.0f;  // 1/sqrt(64*9)
    const float wv = w[b * CINN + cin] * scale;

    float v[9];
    float ss = 0.0f;
#pragma unroll
    for (int kk = 0; kk < 9; ++kk) {
        float t = weight[(cout * CINN + cin) * 9 + kk] * wv;
        v[kk] = t;
        ss += t * t;
    }

    __shared__ float red[64];
    red[cin] = ss;
    __syncthreads();
    if (cin < 32) {
        float s = red[cin] + red[cin + 32];
#pragma unroll
        for (int off = 16; off > 0; off >>= 1)
            s += __shfl_down_sync(0xffffffffu, s, off);
        if (cin == 0) red[0] = s;
    }
    __syncthreads();

    const float d = rsqrtf(red[0] + 1e-8f);
    const int ch = cin >> 4;
    const int kh = (cin >> 3) & 1;
    const int ki = cin & 7;
#pragma unroll
    for (int kk = 0; kk < 9; ++kk) {
        g_wsh[((((((size_t)b * NCH + ch) * 9 + kk) * 2 + kh) * 64) + cout) * 8 + ki] =
            __float2half_rn(v[kk] * d);
    }
}

// ---------------------------------------------------------------------------
// Kernel 2: FP16 mma.sync implicit-GEMM conv, ldmatrix + cp.async,
// with register-fragment double buffering across taps.
// grid (512 y, 8 b), 256 threads (8 warps), 1 CTA/SM.
// ---------------------------------------------------------------------------
__global__ void __launch_bounds__(256)
conv_mma_kernel(float* __restrict__ out) {
    extern __shared__ char smem[];
    const uint32_t sw = smem_u32(smem);
    const uint32_t sx = sw + W_BYTES;

    const int y = blockIdx.x;
    const int b = blockIdx.y;

    const int tid  = threadIdx.x;
    const int wid  = tid >> 5;     // pixel 64-group
    const int lane = tid & 31;
    const int t    = lane & 3;
    const int g    = lane >> 2;
    const int W0   = wid * 64;

    float acc[4][8][4];
#pragma unroll
    for (int mt = 0; mt < 4; ++mt)
#pragma unroll
        for (int nt = 0; nt < 8; ++nt)
#pragma unroll
            for (int i = 0; i < 4; ++i) acc[mt][nt][i] = 0.0f;

    // per-lane static ldmatrix address parts
    const uint32_t aw_lane = sw + (uint32_t)((lane >> 4) * 1024 + (lane & 15) * 16);
    const uint32_t xb_lane = (uint32_t)(((lane >> 3) & 1) * XPLANE +
                                        (W0 + (lane & 7) + ((lane >> 4) << 3)) * 16);

    // ---- weight fill: all 4 chunks, once ----
    {
        const char* wsrc = (const char*)g_wsh + (size_t)b * W_BYTES;
#pragma unroll
        for (int k = 0; k < 18; ++k) {
            const int idx = tid + k * 256;
            cp16(sw + idx * 16, wsrc + (size_t)idx * 16);
        }
    }

    // ---- x stage fill ----
    auto fill_x = [&](int ch, int stage) {
        const uint32_t ss = sx + stage * XSTAGE;
#pragma unroll
        for (int row = 0; row < 3; ++row) {
            const int yy  = y + row - 1;
            const bool yok = ((unsigned)yy < (unsigned)HH);
            const __half* src =
                g_xh + (((size_t)b * HH + (yok ? yy : 0)) * WWW) * CINN + ch * 16;
            const uint32_t dst0 = ss + row * XROW_BYTES;
#pragma unroll
            for (int i = tid; i < 514 * 2; i += 256) {
                const int px   = i >> 1;
                const int half = i & 1;
                const int gx   = px - 1;
                const bool ok  = yok && ((unsigned)gx < (unsigned)WWW);
                const int gxc  = gx < 0 ? 0 : (gx > WWW - 1 ? WWW - 1 : gx);
                cp16z(dst0 + half * XPLANE + px * 16,
                      src + (size_t)gxc * CINN + half * 8, ok ? 16u : 0u);
            }
        }
    };

    // ---- fragment loader for one tap ----
    auto load_frags = [&](uint32_t awc, uint32_t abs0, int tap,
                          uint32_t A[4][4], uint32_t Bf[4][4]) {
        const int dy = tap / 3;
        const int dx = tap - dy * 3;
        const uint32_t aw = awc + (uint32_t)tap * 2048;
        const uint32_t ab = abs0 + (uint32_t)dy * XROW_BYTES + (uint32_t)dx * 16;
#pragma unroll
        for (int np = 0; np < 4; ++np)
            ldsm4(Bf[np][0], Bf[np][1], Bf[np][2], Bf[np][3],
                  ab + (uint32_t)(np * 256));
#pragma unroll
        for (int mt = 0; mt < 4; ++mt)
            ldsm4(A[mt][0], A[mt][1], A[mt][2], A[mt][3],
                  aw + (uint32_t)(mt * 256));
    };

    // ---- MMA on loaded fragments ----
    auto do_mmas = [&](uint32_t A[4][4], uint32_t Bf[4][4]) {
#pragma unroll
        for (int np = 0; np < 4; ++np)
#pragma unroll
            for (int mt = 0; mt < 4; ++mt) {
                mma_f16(acc[mt][2 * np + 0], A[mt][0], A[mt][1], A[mt][2],
                        A[mt][3], Bf[np][0], Bf[np][1]);
                mma_f16(acc[mt][2 * np + 1], A[mt][0], A[mt][1], A[mt][2],
                        A[mt][3], Bf[np][2], Bf[np][3]);
            }
    };

    // ---- compute one 16-cin chunk, tap-level fragment double buffering ----
    auto compute = [&](int ch, int stage) {
        const uint32_t awc  = aw_lane + (uint32_t)(ch * 9 * 2048);
        const uint32_t abs0 = sx + stage * XSTAGE + xb_lane;

        uint32_t A[2][4][4], Bf[2][4][4];
        load_frags(awc, abs0, 0, A[0], Bf[0]);
#pragma unroll
        for (int tap = 0; tap < 9; ++tap) {
            if (tap < 8)
                load_frags(awc, abs0, tap + 1, A[(tap + 1) & 1], Bf[(tap + 1) & 1]);
            do_mmas(A[tap & 1], Bf[tap & 1]);
        }
    };

    // ---- pipeline: weights+stage0 in G0; stages 1,2 in G1,G2 ----
    fill_x(0, 0);
    cp_commit();
    fill_x(1, 1);
    cp_commit();
    fill_x(2, 2);
    cp_commit();

#pragma unroll 1
    for (int ch = 0; ch < NCH; ++ch) {
        if (ch <= 1) cp_wait<2>();
        else if (ch == 2) cp_wait<1>();
        else cp_wait<0>();
        __syncthreads();
        compute(ch, ch % 3);
        if (ch == 0) {           // only ch=0 refills a stage (chunk 3 -> stage 0)
            __syncthreads();
            fill_x(3, 0);
            cp_commit();
        }
    }

    // ---- epilogue: float2 stores ----
#pragma unroll
    for (int mt = 0; mt < 4; ++mt) {
        const int cout0 = mt * 16 + g;
#pragma unroll
        for (int nt = 0; nt < 8; ++nt) {
            const int px = W0 + nt * 8 + 2 * t;
            float* p0 = out + (((size_t)(b * COUTN + cout0)) * HH + y) * WWW + px;
            float* p1 = out + (((size_t)(b * COUTN + cout0 + 8)) * HH + y) * WWW + px;
            *(float2*)p0 = make_float2(acc[mt][nt][0], acc[mt][nt][1]);
            *(float2*)p1 = make_float2(acc[mt][nt][2], acc[mt][nt][3]);
        }
    }
}

// ---------------------------------------------------------------------------
extern "C" void kernel_launch(void* const* d_in, const int* in_sizes, int n_in,
                              void* d_out, int out_size) {
    const float* x      = (const float*)d_in[0];   // [8,64,512,512]
    const float* w      = (const float*)d_in[1];   // [8,64]
    const float* weight = (const float*)d_in[2];   // [64,64,3,3]
    float* out = (float*)d_out;                    // [8,64,512,512]

    cudaFuncSetAttribute(conv_mma_kernel,
                         cudaFuncAttributeMaxDynamicSharedMemorySize, SMEM_DYN);

    transpose_kernel<<<dim3(WWW / 32, HH, BB), 256>>>(x);
    modulate_kernel<<<dim3(COUTN, BB), 64>>>(w, weight);
    conv_mma_kernel<<<dim3(HH, BB), 256, SMEM_DYN>>>(out);
}